// round 16
// baseline (speedup 1.0000x reference)
#include <cuda_runtime.h>
#include <cuda_bf16.h>
#include <math.h>

// Problem dims
#define Bb 2
#define Cc 512
#define Mm 16
#define Tt 128
#define Hh 8
#define Dd 64
#define Ss 2048           // Mm*Tt
#define Gg 128
#define BSr (Bb*Ss)       // 4096 rows
#define NCONV (Bb*Cc*Ss)
#define NQ (BSr*Cc)
#define WN (Cc*Cc)

typedef __nv_bfloat16 bf16;
typedef __nv_bfloat162 bf162;

// -------- scratch (static device globals; no allocation) --------
__device__ bf16  g_conv[3*NCONV];   // cq | ck | cv   [b][c][s]
__device__ bf16  g_qkv[3*NQ];       // q (row-major, roped+scaled) | kT ([b][c][s], roped) | v (row-major)
__device__ bf16  g_o [NQ];          // attention out, row-major
__device__ bf16  g_w [5*WN];        // pw_q|pw_k|pw_v|attn_w|out_w  (bf16)
__device__ bf16  g_w5[WN];          // fused attn_w @ out_w (bf16)
__device__ float g_b5[Cc];          // fused bias: out_w^T attn_b + out_b

// -------- PTX helpers --------
__device__ __forceinline__ unsigned smem_u32(const void* p) {
    return (unsigned)__cvta_generic_to_shared(p);
}
__device__ __forceinline__ void cp16(void* s, const void* g) {
    asm volatile("cp.async.ca.shared.global [%0],[%1],16;\n"
                 :: "r"(smem_u32(s)), "l"(g));
}
__device__ __forceinline__ void cp_commit() { asm volatile("cp.async.commit_group;\n"); }
template <int N>
__device__ __forceinline__ void cp_wait() { asm volatile("cp.async.wait_group %0;\n" :: "n"(N)); }

__device__ __forceinline__ void ldsm4(unsigned& r0, unsigned& r1, unsigned& r2, unsigned& r3, unsigned a) {
    asm volatile("ldmatrix.sync.aligned.m8n8.x4.shared.b16 {%0,%1,%2,%3},[%4];"
                 : "=r"(r0), "=r"(r1), "=r"(r2), "=r"(r3) : "r"(a));
}
__device__ __forceinline__ void ldsm4t(unsigned& r0, unsigned& r1, unsigned& r2, unsigned& r3, unsigned a) {
    asm volatile("ldmatrix.sync.aligned.m8n8.x4.trans.shared.b16 {%0,%1,%2,%3},[%4];"
                 : "=r"(r0), "=r"(r1), "=r"(r2), "=r"(r3) : "r"(a));
}
__device__ __forceinline__ void mma_bf(float4& d,
    unsigned a0, unsigned a1, unsigned a2, unsigned a3, unsigned b0, unsigned b1)
{
    asm volatile(
      "mma.sync.aligned.m16n8k16.row.col.f32.bf16.bf16.f32 "
      "{%0,%1,%2,%3},{%4,%5,%6,%7},{%8,%9},{%0,%1,%2,%3};"
      : "+f"(d.x), "+f"(d.y), "+f"(d.z), "+f"(d.w)
      : "r"(a0), "r"(a1), "r"(a2), "r"(a3), "r"(b0), "r"(b1));
}
__device__ __forceinline__ bf16 tob(float x) { return __float2bfloat16(x); }
// pack two f32 into bf16x2 (lo in lower halfword)
__device__ __forceinline__ unsigned cvtpack(float lo, float hi) {
    unsigned r;
    asm("cvt.rn.bf16x2.f32 %0,%1,%2;" : "=r"(r) : "f"(hi), "f"(lo));
    return r;
}
// 2^x on a bf16x2 pair
__device__ __forceinline__ unsigned ex2b(unsigned x) {
    unsigned r;
    asm("ex2.approx.ftz.bf16x2 %0,%1;" : "=r"(r) : "r"(x));
    return r;
}
// acc element select (compile-time hh/cc)
__device__ __forceinline__ float fsel(const float4& f, int hh, int cc) {
    return hh ? (cc ? f.w : f.z) : (cc ? f.y : f.x);
}

#define ROPE_LN 0.5756462732485114f   // ln(10000)/16
#define QSC 0.18033688011112042f      // 0.125 * log2(e)
#define ONESB 0x3F803F80u             // bf16x2 {1.0, 1.0}

// ---------------- Fused GroupNorm + depthwise 3x3 (q/k/v), bf16 out ----------------
// One block per (b, g): 4 channels x 2048 positions. 512 threads.
__global__ void __launch_bounds__(512)
gndw_kernel(const float* __restrict__ x,
            const float* __restrict__ scale, const float* __restrict__ bias,
            const float* __restrict__ dwq, const float* __restrict__ dwk,
            const float* __restrict__ dwv)
{
    __shared__ float xt[4][Ss];
    const int bg = blockIdx.x;            // 0..255
    const int g  = bg & (Gg - 1);
    const int b  = bg >> 7;
    const float* src = x + (size_t)bg * 8192;

    float s = 0.f, s2 = 0.f;
    for (int i = threadIdx.x; i < 8192; i += 512) {
        float v = src[i];
        xt[i >> 11][i & 2047] = v;
        s += v; s2 += v * v;
    }
    for (int off = 16; off > 0; off >>= 1) {
        s  += __shfl_down_sync(0xffffffffu, s,  off);
        s2 += __shfl_down_sync(0xffffffffu, s2, off);
    }
    __shared__ float ws[16], ws2[16];
    int wid = threadIdx.x >> 5, lane = threadIdx.x & 31;
    if (lane == 0) { ws[wid] = s; ws2[wid] = s2; }
    __syncthreads();
    float S1 = 0.f, S2 = 0.f;
#pragma unroll
    for (int i = 0; i < 16; i++) { S1 += ws[i]; S2 += ws2[i]; }
    const float mean = S1 * (1.0f / 8192.0f);
    const float var  = S2 * (1.0f / 8192.0f) - mean * mean;
    const float rstd = rsqrtf(var + 1e-5f);

    for (int i = threadIdx.x; i < 8192; i += 512) {
        int c4 = i >> 11;
        xt[c4][i & 2047] = (xt[c4][i & 2047] - mean) * rstd * scale[g * 4 + c4]
                           + bias[g * 4 + c4];
    }
    __syncthreads();

#pragma unroll 1
    for (int c4 = 0; c4 < 4; c4++) {
        const int c = g * 4 + c4;
        float wq[9], wk[9], wv[9];
#pragma unroll
        for (int i = 0; i < 9; i++) {
            wq[i] = dwq[i * Cc + c];
            wk[i] = dwk[i * Cc + c];
            wv[i] = dwv[i * Cc + c];
        }
        for (int i = threadIdx.x; i < Ss; i += 512) {
            int m = i >> 7, t = i & 127;
            float aq = 0.f, ak = 0.f, av = 0.f;
#pragma unroll
            for (int dm = -1; dm <= 1; dm++) {
#pragma unroll
                for (int dt = -1; dt <= 1; dt++) {
                    int mm = m + dm, tt = t + dt;
                    if (mm >= 0 && mm < Mm && tt >= 0 && tt < Tt) {
                        float xv = xt[c4][mm * Tt + tt];
                        int wi = (dm + 1) * 3 + (dt + 1);
                        aq = fmaf(xv, wq[wi], aq);
                        ak = fmaf(xv, wk[wi], ak);
                        av = fmaf(xv, wv[wi], av);
                    }
                }
            }
            size_t off = ((size_t)(b * Cc + c)) * Ss + i;
            g_conv[off]                    = tob(aq);
            g_conv[off + (size_t)NCONV]    = tob(ak);
            g_conv[off + 2*(size_t)NCONV]  = tob(av);
        }
    }
}

// ---------------- Weight convert: 5 x (512x512) fp32 -> bf16 ----------------
__global__ void wconv_kernel(const float* __restrict__ w0, const float* __restrict__ w1,
                             const float* __restrict__ w2, const float* __restrict__ w3,
                             const float* __restrict__ w4)
{
    int idx = blockIdx.x * 256 + threadIdx.x;
    int base = idx * 4;
    if (base >= 5 * WN) return;
    int wsel = base / WN, off = base % WN;
    const float* src = (wsel == 0) ? w0 : (wsel == 1) ? w1 : (wsel == 2) ? w2
                     : (wsel == 3) ? w3 : w4;
    float4 v = *(const float4*)(src + off);
    bf162 lo; lo.x = tob(v.x); lo.y = tob(v.y);
    bf162 hi; hi.x = tob(v.z); hi.y = tob(v.w);
    *(bf162*)(g_w + base)     = lo;
    *(bf162*)(g_w + base + 2) = hi;
}

// ---------------- Fused bias: b5 = out_w^T attn_b + out_b (f32) ----------------
__global__ void __launch_bounds__(512)
b5_kernel(const float* __restrict__ attn_b, const float* __restrict__ out_w,
          const float* __restrict__ out_b)
{
    const int j = threadIdx.x;           // one block of 512
    float acc = out_b[j];
    for (int k = 0; k < Cc; k++)
        acc = fmaf(attn_b[k], out_w[k * Cc + j], acc);
    g_b5[j] = acc;
}

// ---------------- bf16 GEMM: 128x128 per block, BK=32, 256 threads ----------
// 8 warps as 2(row) x 4(col). ROPE: 0 none; 1 rotate (q also pre-scaled by QSC).
#define APc 136
#define APr 40
#define BPp 136
template <bool IN_CM, bool OUT_CM, bool BIAS, bool RES, bool OUTF32, int ROPE>
__device__ __forceinline__ void gemm_body(
    const bf16* __restrict__ A, const bf16* __restrict__ W,
    const float* __restrict__ bias, const float* __restrict__ res,
    void* __restrict__ outv, int row0, int col0)
{
    __shared__ __align__(16) bf16 As[2][5120];     // max(32*136, 128*40)
    __shared__ __align__(16) bf16 Bs[2][32 * BPp];
    const int tid = threadIdx.x;
    const int w = tid >> 5, lane = tid & 31, g = lane >> 2, t = lane & 3;
    const int wr = w >> 2, wc = w & 3;
    const int b = row0 >> 11, sb = row0 & (Ss - 1);
    const bf16* Abase = IN_CM ? (A + (size_t)b * Cc * Ss + sb)
                              : (A + (size_t)row0 * Cc);

    float4 acc[4][4];
#pragma unroll
    for (int i = 0; i < 4; i++)
#pragma unroll
        for (int j = 0; j < 4; j++) acc[i][j] = make_float4(0.f, 0.f, 0.f, 0.f);

    auto ISSUE = [&](int k0, int buf) {
        bf16* as = As[buf]; bf16* bs = Bs[buf];
        if (IN_CM) {
#pragma unroll
            for (int q2 = 0; q2 < 2; q2++) {
                int c = tid + q2 * 256;
                int kk = c >> 4, s8 = c & 15;
                cp16(as + kk * APc + s8 * 8, Abase + (size_t)(k0 + kk) * Ss + s8 * 8);
            }
        } else {
#pragma unroll
            for (int q2 = 0; q2 < 2; q2++) {
                int c = tid + q2 * 256;
                int rr = c >> 2, k8 = c & 3;
                cp16(as + rr * APr + k8 * 8, Abase + (size_t)rr * Cc + k0 + k8 * 8);
            }
        }
#pragma unroll
        for (int q2 = 0; q2 < 2; q2++) {
            int c = tid + q2 * 256;
            int kk = c >> 4, n8 = c & 15;
            cp16(bs + kk * BPp + n8 * 8, W + (size_t)(k0 + kk) * Cc + col0 + n8 * 8);
        }
        cp_commit();
    };

    auto COMPUTE = [&](int buf) {
        const bf16* as = As[buf]; const bf16* bs = Bs[buf];
#pragma unroll
        for (int ks = 0; ks < 32; ks += 16) {
            unsigned a[4][4];
#pragma unroll
            for (int rt = 0; rt < 4; rt++) {
                if (IN_CM) {
                    int k  = ks + ((lane >> 4) << 3) + (lane & 7);
                    int ro = wr * 64 + rt * 16 + ((lane >> 3) & 1) * 8;
                    ldsm4t(a[rt][0], a[rt][1], a[rt][2], a[rt][3],
                           smem_u32(as + k * APc + ro));
                } else {
                    int r = wr * 64 + rt * 16 + (lane & 15);
                    int k = ks + ((lane >> 4) << 3);
                    ldsm4(a[rt][0], a[rt][1], a[rt][2], a[rt][3],
                          smem_u32(as + r * APr + k));
                }
            }
#pragma unroll
            for (int p = 0; p < 2; p++) {
                unsigned bfr[4];
                int k = ks + (lane & 15);
                int n = wc * 32 + p * 16 + ((lane >> 4) << 3);
                ldsm4t(bfr[0], bfr[1], bfr[2], bfr[3], smem_u32(bs + k * BPp + n));
#pragma unroll
                for (int h2 = 0; h2 < 2; h2++) {
                    int nt = p * 2 + h2;
#pragma unroll
                    for (int rt = 0; rt < 4; rt++)
                        mma_bf(acc[rt][nt], a[rt][0], a[rt][1], a[rt][2], a[rt][3],
                               bfr[h2 * 2], bfr[h2 * 2 + 1]);
                }
            }
        }
    };

    ISSUE(0, 0);
#pragma unroll 1
    for (int kt = 0; kt < 16; kt++) {
        if (kt < 15) { ISSUE((kt + 1) * 32, (kt + 1) & 1); cp_wait<1>(); }
        else         { cp_wait<0>(); }
        __syncthreads();
        COMPUTE(kt & 1);
        __syncthreads();
    }

    // ---------------- epilogues ----------------
    if (ROPE == 1 && !OUT_CM) {
        // q: rotate pairs p=0 <-> p=1 and pre-scale by QSC
        bf16* out = (bf16*)outv;
        const int half = wc & 1;      // 0: f-half (pos=m), 1: t-half (pos=t)
#pragma unroll
        for (int h2 = 0; h2 < 2; h2++) {
            const int colb = col0 + wc * 32 + h2 * 8 + 2 * t;
            float inv0 = expf(-(float)(h2 * 8 + 2 * t)     * ROPE_LN);
            float inv1 = expf(-(float)(h2 * 8 + 2 * t + 1) * ROPE_LN);
#pragma unroll
            for (int rt = 0; rt < 4; rt++)
#pragma unroll
            for (int hh = 0; hh < 2; hh++) {
                const int row = row0 + wr * 64 + rt * 16 + g + hh * 8;
                const int sI = row & 2047;
                const float pos = half ? (float)(sI & 127) : (float)(sI >> 7);
                float olo[2], ohi[2];
#pragma unroll
                for (int cc = 0; cc < 2; cc++) {
                    float ang = pos * (cc ? inv1 : inv0);
                    float cv = cosf(ang), sv = sinf(ang);
                    float v1 = fsel(acc[rt][h2],     hh, cc);
                    float v2 = fsel(acc[rt][2 + h2], hh, cc);
                    olo[cc] = (v1 * cv - v2 * sv) * QSC;
                    ohi[cc] = (v1 * sv + v2 * cv) * QSC;
                }
                bf162 lo; lo.x = tob(olo[0]); lo.y = tob(olo[1]);
                bf162 hi; hi.x = tob(ohi[0]); hi.y = tob(ohi[1]);
                *(bf162*)(out + (size_t)row * Cc + colb)      = lo;
                *(bf162*)(out + (size_t)row * Cc + colb + 16) = hi;
            }
        }
    } else if (ROPE == 1 && OUT_CM) {
        // k: rotate + write transposed [b][c][s]
        bf16* out = (bf16*)outv;
        const int half = wc & 1;
#pragma unroll
        for (int h2 = 0; h2 < 2; h2++)
#pragma unroll
        for (int cc = 0; cc < 2; cc++) {
            const int col = col0 + wc * 32 + h2 * 8 + 2 * t + cc;
            const float inv = expf(-(float)(h2 * 8 + 2 * t + cc) * ROPE_LN);
#pragma unroll
            for (int rt = 0; rt < 4; rt++)
#pragma unroll
            for (int hh = 0; hh < 2; hh++) {
                const int sI = sb + wr * 64 + rt * 16 + g + hh * 8;
                const float pos = half ? (float)(sI & 127) : (float)(sI >> 7);
                float ang = pos * inv;
                float cv = cosf(ang), sv = sinf(ang);
                float v1 = fsel(acc[rt][h2],     hh, cc);
                float v2 = fsel(acc[rt][2 + h2], hh, cc);
                out[(size_t)b * Cc * Ss + (size_t)col * Ss + sI]        = tob(v1 * cv - v2 * sv);
                out[(size_t)b * Cc * Ss + (size_t)(col + 16) * Ss + sI] = tob(v1 * sv + v2 * cv);
            }
        }
    } else if (!OUT_CM) {
        bf16* out = (bf16*)outv;
#pragma unroll
        for (int p = 0; p < 2; p++)
#pragma unroll
        for (int h2 = 0; h2 < 2; h2++) {
            int nt = p * 2 + h2;
            int col = col0 + wc * 32 + p * 16 + h2 * 8 + 2 * t;
            float b0v = BIAS ? bias[col] : 0.f, b1v = BIAS ? bias[col + 1] : 0.f;
#pragma unroll
            for (int rt = 0; rt < 4; rt++) {
                int row = row0 + wr * 64 + rt * 16 + g;
                bf162 lo; lo.x = tob(acc[rt][nt].x + b0v); lo.y = tob(acc[rt][nt].y + b1v);
                bf162 hi; hi.x = tob(acc[rt][nt].z + b0v); hi.y = tob(acc[rt][nt].w + b1v);
                *(bf162*)(out + (size_t)row * Cc + col)       = lo;
                *(bf162*)(out + (size_t)(row + 8) * Cc + col) = hi;
            }
        }
    } else {
        // OUT_CM fp32 (+bias, +residual) -- final output
#pragma unroll
        for (int p = 0; p < 2; p++)
#pragma unroll
        for (int h2 = 0; h2 < 2; h2++) {
            int nt = p * 2 + h2;
            int colb = col0 + wc * 32 + p * 16 + h2 * 8 + 2 * t;
#pragma unroll
            for (int cc2 = 0; cc2 < 2; cc2++) {
                int col = colb + cc2;
                float bb = BIAS ? bias[col] : 0.f;
#pragma unroll
                for (int rt = 0; rt < 4; rt++) {
                    size_t off = (size_t)b * Cc * Ss + (size_t)col * Ss
                               + sb + wr * 64 + rt * 16 + g;
                    float v0 = (cc2 == 0 ? acc[rt][nt].x : acc[rt][nt].y) + bb;
                    float v8 = (cc2 == 0 ? acc[rt][nt].z : acc[rt][nt].w) + bb;
                    float* out = (float*)outv;
                    if (RES) { v0 += res[off]; v8 += res[off + 8]; }
                    out[off]     = v0;
                    out[off + 8] = v8;
                }
            }
        }
    }
}

template <bool IN_CM, bool OUT_CM, bool BIAS, bool RES, bool OUTF32, int ROPE>
__global__ void __launch_bounds__(256)
gemm_kernel(const bf16* __restrict__ A, const bf16* __restrict__ W,
            const float* __restrict__ bias, const float* __restrict__ res,
            void* __restrict__ out)
{
    gemm_body<IN_CM, OUT_CM, BIAS, RES, OUTF32, ROPE>(A, W, bias, res, out,
                                                      blockIdx.y * 128, blockIdx.x * 128);
}

// QKV fused over blockIdx.z. q: rope+scale; k: rope + transposed out; v: plain.
__global__ void __launch_bounds__(256)
gemm_qkv_kernel()
{
    const int z = blockIdx.z;
    const int row0 = blockIdx.y * 128, col0 = blockIdx.x * 128;
    if (z == 0) {
        gemm_body<true, false, false, false, false, 1>(
            g_conv, g_w, nullptr, nullptr, g_qkv, row0, col0);
    } else if (z == 1) {
        gemm_body<true, true, false, false, false, 1>(
            g_conv + (size_t)NCONV, g_w + WN, nullptr, nullptr,
            g_qkv + (size_t)NQ, row0, col0);
    } else {
        gemm_body<true, false, false, false, false, 0>(
            g_conv + 2 * (size_t)NCONV, g_w + 2 * (size_t)WN, nullptr, nullptr,
            g_qkv + 2 * (size_t)NQ, row0, col0);
    }
}

// ---------------- Flash attention, bf16 mma, 4 warps x 2 row-tiles ----------------
// grid (S/128, B*H), 128 threads (4 warps). Br=128, Bc=128 (= one T window), D=64.
// Warp w owns q-rows [w*32, w*32+32) as TWO m16 row-tiles -> each K/V ldmatrix
// feeds mma for both tiles. Q pre-scaled by 0.125*log2(e);
// P = ex2.approx.ftz.bf16x2(S); mask via AND; row sums via ones-mma.
// K/V double-buffered cp.async.
#define QSP 40
#define KPP2 136
#define VSP 72
#define SM_Q (128 * QSP)    // 5120 bf16
#define SM_K (64 * KPP2)    // 8704 bf16
#define SM_V (128 * VSP)    // 9216 bf16
#define ATTN_SMEM_BYTES ((SM_Q + 2 * SM_K + 2 * SM_V) * 2)   // 81920 B

__global__ void __launch_bounds__(128)
attn_kernel(const int* __restrict__ lengths)
{
    extern __shared__ __align__(16) bf16 sm[];
    bf16* Qs = sm;
    bf16* Kbuf[2] = { sm + SM_Q, sm + SM_Q + SM_K };
    bf16* Vbuf[2] = { sm + SM_Q + 2 * SM_K, sm + SM_Q + 2 * SM_K + SM_V };

    const bf16* q  = g_qkv;
    const bf16* kT = g_qkv + (size_t)NQ;
    const bf16* v  = g_qkv + 2 * (size_t)NQ;

    const int bh = blockIdx.y;
    const int b = bh >> 3, h = bh & 7;
    const int q0 = blockIdx.x * 128;
    const int len = lengths[b];
    const int tid = threadIdx.x;
    const int w = tid >> 5, lane = tid & 31, g = lane >> 2, t = lane & 3;
    const int r0 = w * 32;

    // halfword masks for the maskable column range (p = 4..7)
    unsigned mlo[4], mhi[4];
#pragma unroll
    for (int i = 0; i < 4; i++) {
        int c0 = (4 + i) * 16 + 2 * t;
        mlo[i] = (c0 < len ? 0x0000FFFFu : 0u) | (c0 + 1 < len ? 0xFFFF0000u : 0u);
        int c1 = c0 + 8;
        mhi[i] = (c1 < len ? 0x0000FFFFu : 0u) | (c1 + 1 < len ? 0xFFFF0000u : 0u);
    }

    // Q tile (row-major [r][d]) via cp.async -- group 0
#pragma unroll
    for (int q2 = 0; q2 < 8; q2++) {
        int c = tid + q2 * 128;
        int r = c >> 3, d8 = c & 7;
        cp16(Qs + r * QSP + d8 * 8,
             q + ((size_t)(b * Ss + q0 + r)) * Cc + h * Dd + d8 * 8);
    }
    cp_commit();

    auto ISSUE_KV = [&](int kt, int buf) {
        const int kb = kt * 128;
        bf16* K = Kbuf[buf]; bf16* V = Vbuf[buf];
#pragma unroll
        for (int q2 = 0; q2 < 8; q2++) {
            int c = tid + q2 * 128;
            int d = c >> 4, s8 = c & 15;
            cp16(K + d * KPP2 + s8 * 8,
                 kT + ((size_t)(b * Cc + h * Dd + d)) * Ss + kb + s8 * 8);
        }
#pragma unroll
        for (int q2 = 0; q2 < 8; q2++) {
            int c = tid + q2 * 128;
            int r = c >> 3, d8 = c & 7;
            cp16(V + r * VSP + d8 * 8,
                 v + ((size_t)(b * Ss + kb + r)) * Cc + h * Dd + d8 * 8);
        }
        cp_commit();
    };

    ISSUE_KV(0, 0);     // group 1
    cp_wait<1>();       // Q arrived
    __syncthreads();

    // cache Q fragments in registers (whole kernel): 2 row-tiles
    unsigned qf[2][4][4];
#pragma unroll
    for (int rt = 0; rt < 2; rt++)
#pragma unroll
    for (int d0 = 0; d0 < 4; d0++) {
        int r = r0 + rt * 16 + (lane & 15);
        int k = d0 * 16 + ((lane >> 4) << 3);
        ldsm4(qf[rt][d0][0], qf[rt][d0][1], qf[rt][d0][2], qf[rt][d0][3],
              smem_u32(Qs + r * QSP + k));
    }

    float4 Of[2][8];
#pragma unroll
    for (int rt = 0; rt < 2; rt++)
#pragma unroll
    for (int i = 0; i < 8; i++) Of[rt][i] = make_float4(0.f, 0.f, 0.f, 0.f);
    float4 Lf[2];
    Lf[0] = make_float4(0.f, 0.f, 0.f, 0.f);
    Lf[1] = make_float4(0.f, 0.f, 0.f, 0.f);

#pragma unroll 1
    for (int kt = 0; kt < Ss / 128; kt++) {
        cp_wait<0>();
        __syncthreads();
        if (kt < 15) ISSUE_KV(kt + 1, (kt + 1) & 1);
        const bf16* K = Kbuf[kt & 1];
        const bf16* V = Vbuf[kt & 1];

        // per 16-col block p: S (both row-tiles) -> ex2 -> mask -> L-mma -> PV
#pragma unroll
        for (int p = 0; p < 8; p++) {
            float4 S0[2], S1[2];
#pragma unroll
            for (int rt = 0; rt < 2; rt++) {
                S0[rt] = make_float4(0.f, 0.f, 0.f, 0.f);
                S1[rt] = make_float4(0.f, 0.f, 0.f, 0.f);
            }
#pragma unroll
            for (int d0 = 0; d0 < 4; d0++) {
                unsigned bfr[4];
                int dd = d0 * 16 + (lane & 15);
                int n = p * 16 + ((lane >> 4) << 3);
                ldsm4t(bfr[0], bfr[1], bfr[2], bfr[3], smem_u32(K + dd * KPP2 + n));
#pragma unroll
                for (int rt = 0; rt < 2; rt++) {
                    mma_bf(S0[rt], qf[rt][d0][0], qf[rt][d0][1], qf[rt][d0][2], qf[rt][d0][3],
                           bfr[0], bfr[1]);
                    mma_bf(S1[rt], qf[rt][d0][0], qf[rt][d0][1], qf[rt][d0][2], qf[rt][d0][3],
                           bfr[2], bfr[3]);
                }
            }
            // P = 2^S per row-tile; already A-fragment layout
            unsigned pa[2][4];
#pragma unroll
            for (int rt = 0; rt < 2; rt++) {
                pa[rt][0] = ex2b(cvtpack(S0[rt].x, S0[rt].y));   // row g,   k 2t,2t+1
                pa[rt][1] = ex2b(cvtpack(S0[rt].z, S0[rt].w));   // row g+8, k 2t,2t+1
                pa[rt][2] = ex2b(cvtpack(S1[rt].x, S1[rt].y));   // row g,   k 8+2t
                pa[rt][3] = ex2b(cvtpack(S1[rt].z, S1[rt].w));   // row g+8, k 8+2t
                if (p >= 4) {
                    pa[rt][0] &= mlo[p - 4]; pa[rt][1] &= mlo[p - 4];
                    pa[rt][2] &= mhi[p - 4]; pa[rt][3] &= mhi[p - 4];
                }
                mma_bf(Lf[rt], pa[rt][0], pa[rt][1], pa[rt][2], pa[rt][3], ONESB, ONESB);
            }
            // O += P V  (V fragments shared across the two row-tiles)
#pragma unroll
            for (int pd = 0; pd < 4; pd++) {
                unsigned vb[4];
                int kk = p * 16 + (lane & 15);
                int n2 = pd * 16 + ((lane >> 4) << 3);
                ldsm4t(vb[0], vb[1], vb[2], vb[3], smem_u32(V + kk * VSP + n2));
#pragma unroll
                for (int rt = 0; rt < 2; rt++) {
                    mma_bf(Of[rt][pd * 2],     pa[rt][0], pa[rt][1], pa[rt][2], pa[rt][3],
                           vb[0], vb[1]);
                    mma_bf(Of[rt][pd * 2 + 1], pa[rt][0], pa[rt][1], pa[rt][2], pa[rt][3],
                           vb[2], vb[3]);
                }
            }
        }
    }

    // write O (bf16 row-major); Lf[rt].x/.z are quad-complete row sums
#pragma unroll
    for (int rt = 0; rt < 2; rt++) {
        const float ilA = 1.f / Lf[rt].x, ilB = 1.f / Lf[rt].z;
#pragma unroll
        for (int pd = 0; pd < 4; pd++)
#pragma unroll
        for (int h2 = 0; h2 < 2; h2++) {
            int nt = pd * 2 + h2;
            int d = pd * 16 + h2 * 8 + 2 * t;
            bf162 vA; vA.x = tob(Of[rt][nt].x * ilA); vA.y = tob(Of[rt][nt].y * ilA);
            bf162 vB; vB.x = tob(Of[rt][nt].z * ilB); vB.y = tob(Of[rt][nt].w * ilB);
            size_t rowA = (size_t)(b * Ss + q0 + r0 + rt * 16 + g);
            *(bf162*)(g_o + rowA * Cc + h * Dd + d)           = vA;
            *(bf162*)(g_o + (rowA + 8) * Cc + h * Dd + d)     = vB;
        }
    }
}

// ---------------- launch ----------------
extern "C" void kernel_launch(void* const* d_in, const int* in_sizes, int n_in,
                              void* d_out, int out_size)
{
    const float* x        = (const float*)d_in[0];
    const int*   lengths  = (const int*)  d_in[1];
    const float* gn_scale = (const float*)d_in[2];
    const float* gn_bias  = (const float*)d_in[3];
    const float* dw_q     = (const float*)d_in[4];
    const float* dw_k     = (const float*)d_in[5];
    const float* dw_v     = (const float*)d_in[6];
    const float* pw_q     = (const float*)d_in[7];
    const float* pw_k     = (const float*)d_in[8];
    const float* pw_v     = (const float*)d_in[9];
    const float* attn_w   = (const float*)d_in[10];
    const float* attn_b   = (const float*)d_in[11];
    const float* out_w    = (const float*)d_in[12];
    const float* out_b    = (const float*)d_in[13];
    float* out = (float*)d_out;
    (void)in_sizes; (void)n_in; (void)out_size;

    bf16 *p_o, *p_w, *p_w5;
    float *p_b5;
    cudaGetSymbolAddress((void**)&p_o,  g_o);
    cudaGetSymbolAddress((void**)&p_w,  g_w);
    cudaGetSymbolAddress((void**)&p_w5, g_w5);
    cudaGetSymbolAddress((void**)&p_b5, g_b5);

    cudaFuncSetAttribute(attn_kernel,
                         cudaFuncAttributeMaxDynamicSharedMemorySize,
                         ATTN_SMEM_BYTES);

    wconv_kernel<<<1280, 256>>>(pw_q, pw_k, pw_v, attn_w, out_w);
    // W5 = attn_w @ out_w (bf16, 512x512x512) -- reuses the GEMM template
    gemm_kernel<false, false, false, false, false, 0><<<dim3(Cc / 128, Cc / 128), 256>>>(
        p_w + 3 * (size_t)WN, p_w + 4 * (size_t)WN, nullptr, nullptr, p_w5);
    b5_kernel<<<1, 512>>>(attn_b, out_w, out_b);

    gndw_kernel<<<Bb * Gg, 512>>>(x, gn_scale, gn_bias, dw_q, dw_k, dw_v);

    dim3 qkvgrid(Cc / 128, BSr / 128, 3);
    gemm_qkv_kernel<<<qkvgrid, 256>>>();

    attn_kernel<<<dim3(Ss / 128, Bb * Hh), 128, ATTN_SMEM_BYTES>>>(lengths);

    // out = o @ W5 + b5 + x   (single fused tail GEMM)
    gemm_kernel<false, true, true, true, true, 0><<<dim3(Cc / 128, BSr / 128), 256>>>(
        p_o, p_w5, p_b5, x, out);
}